// round 1
// baseline (speedup 1.0000x reference)
#include <cuda_runtime.h>
#include <math.h>

#define HGT   64
#define WID   64
#define CH    256
#define BATCH 4
#define HW    (HGT*WID)
#define RAD   3
#define NK    49
#define NCOL  70     // 64 + 6 neighborhood columns
#define CHUNK 32

// Pixel-major scratch: [B][HW][C]
__device__ float g_q[BATCH*HW*CH];
__device__ float g_k[BATCH*HW*CH];
__device__ float g_v[BATCH*HW*CH];

// ---------------------------------------------------------------------------
// GEMM: Yt[b][p][o] = sum_c X[b][c][p] * W[o][c]
// BM=128 (pixels), BN=64 (out ch), BK=16, 256 threads, 8x4 microtile.
// ---------------------------------------------------------------------------
__global__ __launch_bounds__(256) void gemm_kernel(
    const float* __restrict__ x,
    const float* __restrict__ w1,
    const float* __restrict__ w2,
    const float* __restrict__ w3)
{
    const int z    = blockIdx.z;       // 0..11
    const int b    = z / 3;
    const int wsel = z - b*3;
    const float* W = (wsel == 0) ? w1 : (wsel == 1 ? w2 : w3);
    float* Y       = (wsel == 0) ? g_q : (wsel == 1 ? g_k : g_v);
    const float* X = x + (size_t)b * CH * HW;
    Y += (size_t)b * HW * CH;

    const int p0 = blockIdx.x * 128;
    const int o0 = blockIdx.y * 64;

    __shared__ float As[16][128];   // [c][p]
    __shared__ float Bs[16][68];    // [c][o], padded stride 68 (16B aligned)

    const int tid = threadIdx.x;
    const int tx  = tid & 15;   // o, 4 each
    const int ty  = tid >> 4;   // p, 8 each

    float acc[8][4];
#pragma unroll
    for (int i = 0; i < 8; i++)
#pragma unroll
        for (int j = 0; j < 4; j++) acc[i][j] = 0.f;

    for (int k0 = 0; k0 < CH; k0 += 16) {
        // Load As: 16 c-rows x 128 p (coalesced float4)
#pragma unroll
        for (int r = 0; r < 2; r++) {
            int idx = tid + r * 256;
            int cr  = idx >> 5;            // 0..15
            int p4  = (idx & 31) << 2;     // 0..124
            float4 v = *(const float4*)(X + (size_t)(k0 + cr) * HW + p0 + p4);
            *(float4*)(&As[cr][p4]) = v;
        }
        // Load Bs transposed: W[o][c] -> Bs[c][o]
        {
            int oo  = tid >> 2;            // 0..63
            int kk4 = (tid & 3) << 2;      // 0,4,8,12
            float4 v = *(const float4*)(W + (size_t)(o0 + oo) * CH + k0 + kk4);
            Bs[kk4 + 0][oo] = v.x;
            Bs[kk4 + 1][oo] = v.y;
            Bs[kk4 + 2][oo] = v.z;
            Bs[kk4 + 3][oo] = v.w;
        }
        __syncthreads();

#pragma unroll
        for (int kk = 0; kk < 16; kk++) {
            float a[8], bb[4];
            float4 a0 = *(const float4*)(&As[kk][ty * 8]);
            float4 a1 = *(const float4*)(&As[kk][ty * 8 + 4]);
            a[0]=a0.x; a[1]=a0.y; a[2]=a0.z; a[3]=a0.w;
            a[4]=a1.x; a[5]=a1.y; a[6]=a1.z; a[7]=a1.w;
            float4 b0 = *(const float4*)(&Bs[kk][tx * 4]);
            bb[0]=b0.x; bb[1]=b0.y; bb[2]=b0.z; bb[3]=b0.w;
#pragma unroll
            for (int i = 0; i < 8; i++)
#pragma unroll
                for (int j = 0; j < 4; j++)
                    acc[i][j] = fmaf(a[i], bb[j], acc[i][j]);
        }
        __syncthreads();
    }

#pragma unroll
    for (int i = 0; i < 8; i++) {
        float4 v = make_float4(acc[i][0], acc[i][1], acc[i][2], acc[i][3]);
        *(float4*)(Y + (size_t)(p0 + ty * 8 + i) * CH + o0 + tx * 4) = v;
    }
}

// ---------------------------------------------------------------------------
// Attention: one block per (b, h) image row. 256 threads.
// Phase 1: logits over C chunks via smem tiles; quad softmax.
// Phase 2: thread = channel; coalesced value gathers; smem-transposed store.
// smem layout (floats): ws[64*52]=3328 | x1s[64*33]=2112 | x2s[490*33]=16170
//                       outS[256*65]=16640 aliases x1s onward.  total 21610 f.
// ---------------------------------------------------------------------------
#define SMEM_FLOATS 21610

__global__ __launch_bounds__(256) void attn_kernel(float* __restrict__ out)
{
    extern __shared__ float smem[];
    float* ws   = smem;             // 64*52
    float* x1s  = smem + 3328;      // 64*33
    float* x2s  = x1s + 2112;       // 490*33
    float* outS = x1s;              // 256*65 (aliases x1s+x2s region)

    const int blk = blockIdx.x;     // b*64 + h
    const int b   = blk >> 6;
    const int h   = blk & 63;
    const int tid = threadIdx.x;
    const size_t rowbase = ((size_t)b * HW + (size_t)h * WID) * CH;

    const int p    = tid >> 2;      // pixel 0..63
    const int part = tid & 3;       // logit partition

    float acc[13];
#pragma unroll
    for (int j = 0; j < 13; j++) acc[j] = 0.f;

    for (int cc = 0; cc < CH; cc += CHUNK) {
        // x1 row tile: 64 px x 32 ch
#pragma unroll
        for (int r = 0; r < 8; r++) {
            int idx = tid + r * 256;
            int px = idx >> 5, c = idx & 31;
            x1s[px * 33 + c] = g_q[rowbase + (size_t)px * CH + cc + c];
        }
        // x2 neighborhood: 7 rows x 70 cols x 32 ch (zero pad OOB)
        for (int idx = tid; idx < 490 * 32; idx += 256) {
            int px = idx >> 5, c = idx & 31;
            int r  = px / NCOL;
            int col = px - r * NCOL;
            int hh = h + r - RAD;
            int wg = col - RAD;
            float v = 0.f;
            if (hh >= 0 && hh < HGT && wg >= 0 && wg < WID)
                v = g_k[((size_t)b * HW + (size_t)hh * WID + wg) * CH + cc + c];
            x2s[px * 33 + c] = v;
        }
        __syncthreads();

        float a[CHUNK];
#pragma unroll
        for (int c = 0; c < CHUNK; c++) a[c] = x1s[p * 33 + c];
#pragma unroll
        for (int j = 0; j < 13; j++) {
            int k = part + 4 * j;
            if (k < NK) {
                int dh = k / 7, dw = k - dh * 7;
                const float* xr = &x2s[(dh * NCOL + p + dw) * 33];
                float s = 0.f;
#pragma unroll
                for (int c = 0; c < CHUNK; c++) s = fmaf(a[c], xr[c], s);
                acc[j] += s;
            }
        }
        __syncthreads();
    }

    // softmax across the 4-thread quad owning pixel p
    float m = -1e30f;
#pragma unroll
    for (int j = 0; j < 13; j++)
        if (part + 4 * j < NK) m = fmaxf(m, acc[j]);
    m = fmaxf(m, __shfl_xor_sync(0xffffffffu, m, 1));
    m = fmaxf(m, __shfl_xor_sync(0xffffffffu, m, 2));

    float e[13];
    float s = 0.f;
#pragma unroll
    for (int j = 0; j < 13; j++) {
        int k = part + 4 * j;
        e[j] = (k < NK) ? __expf(acc[j] - m) : 0.f;
        s += e[j];
    }
    s += __shfl_xor_sync(0xffffffffu, s, 1);
    s += __shfl_xor_sync(0xffffffffu, s, 2);
    float inv = 1.f / s;
#pragma unroll
    for (int j = 0; j < 13; j++) {
        int k = part + 4 * j;
        if (k < NK) ws[p * 52 + k] = e[j] * inv;
    }
    __syncthreads();

    // Phase 2: thread = channel c
    const int c = tid;
    for (int px = 0; px < 64; px++) {
        float o = 0.f;
#pragma unroll
        for (int dh = 0; dh < 7; dh++) {
            int hh = h + dh - RAD;
            if (hh < 0 || hh >= HGT) continue;          // uniform branch
            const float* vrow = &g_v[((size_t)b * HW + (size_t)hh * WID) * CH + c];
            const float* wr   = &ws[px * 52 + dh * 7];
            float t = 0.f;
#pragma unroll
            for (int dw = 0; dw < 7; dw++) {
                int wg = px + dw - RAD;
                if (wg >= 0 && wg < WID)                // uniform branch
                    t = fmaf(wr[dw], vrow[(size_t)wg * CH], t);
            }
            o += t;
        }
        outS[c * 65 + px] = o;
    }
    __syncthreads();

    // Coalesced store to [B,C,H,W]
#pragma unroll
    for (int r = 0; r < 64; r++) {
        int idx = tid + r * 256;
        int cch = idx >> 6, w = idx & 63;
        out[((size_t)(b * CH + cch) * HGT + h) * WID + w] = outS[cch * 65 + w];
    }
}

// ---------------------------------------------------------------------------
extern "C" void kernel_launch(void* const* d_in, const int* in_sizes, int n_in,
                              void* d_out, int out_size)
{
    const float* x  = (const float*)d_in[0];
    const float* w1 = (const float*)d_in[1];
    const float* w2 = (const float*)d_in[2];
    const float* w3 = (const float*)d_in[3];
    float* out = (float*)d_out;
    (void)in_sizes; (void)n_in; (void)out_size;

    static int smem_set = 0;
    // Idempotent host attribute set (not a stream op; safe under capture).
    cudaFuncSetAttribute(attn_kernel,
                         cudaFuncAttributeMaxDynamicSharedMemorySize,
                         SMEM_FLOATS * (int)sizeof(float));
    (void)smem_set;

    dim3 ggrid(HW / 128, CH / 64, BATCH * 3);
    gemm_kernel<<<ggrid, 256>>>(x, w1, w2, w3);

    attn_kernel<<<BATCH * HGT, 256, SMEM_FLOATS * sizeof(float)>>>(out);
}